// round 3
// baseline (speedup 1.0000x reference)
#include <cuda_runtime.h>

#define THREADS 256
#define C16 16
#define DIM 96
#define HW (DIM*DIM)
#define DHW (DIM*DIM*DIM)
#define FEATS 512
#define KTOT 1024
#define KPB 512            // k per block (KSPLIT=2)
#define NB 8               // fixed brick edge
#define PSV (NB*NB*NB)     // 512 voxels per channel
#define BRICK_F (C16*PSV)  // 8192 floats = 32KB

__global__ void __launch_bounds__(THREADS, 5)
obelisk_kernel(const float* __restrict__ vol,
               const float* __restrict__ xyz,
               const float* __restrict__ Amat,
               const float* __restrict__ W6,
               float* __restrict__ out)
{
    __shared__ float brick[BRICK_F];   // 32KB static
    __shared__ float sP[12];
    __shared__ int   sBox[4];          // xlo,ylo,zlo,mode
    __shared__ float sRed[6*8];

    const int tid  = threadIdx.x;
    const int lane = tid & 31;
    const int wid  = tid >> 5;
    const int blk  = blockIdx.x;
    const int pt   = blk >> 1;
    const int kh   = blk & 1;
    const int b    = pt >> 9;
    const int f    = pt & (FEATS - 1);
    const int k0   = kh * KPB;

    if (tid == 0) {
        float x0 = xyz[pt*3+0], x1 = xyz[pt*3+1], x2 = xyz[pt*3+2];
        sP[0] = (x0 + 1.f) * 48.f - 0.5f;
        sP[1] = (x1 + 1.f) * 48.f - 0.5f;
        sP[2] = (x2 + 1.f) * 48.f - 0.5f;
        const float* Ar = Amat + pt * 9;
        sP[3] = 48.f*Ar[6]; sP[4]  = 48.f*Ar[7]; sP[5]  = 48.f*Ar[8];  // x row
        sP[6] = 48.f*Ar[3]; sP[7]  = 48.f*Ar[4]; sP[8]  = 48.f*Ar[5];  // y row
        sP[9] = 48.f*Ar[0]; sP[10] = 48.f*Ar[1]; sP[11] = 48.f*Ar[2];  // z row
    }
    __syncthreads();

    const float bx = sP[0], by = sP[1], bz = sP[2];
    const float ax0 = sP[3], ax1 = sP[4],  ax2 = sP[5];
    const float ay0 = sP[6], ay1 = sP[7],  ay2 = sP[8];
    const float az0 = sP[9], az1 = sP[10], az2 = sP[11];

    // ---------------- Pass 1: bbox of all sample coords (same FP exprs as pass 2)
    float mnx = 1e30f, mxx = -1e30f;
    float mny = 1e30f, mxy = -1e30f;
    float mnz = 1e30f, mxz = -1e30f;
    #pragma unroll
    for (int it = 0; it < 2; it++) {
        int k = k0 + it*THREADS + tid;
        #pragma unroll
        for (int s = 0; s < 2; s++) {
            const float* wp = W6 + s*3*KTOT + k;
            float w0 = __ldg(wp);
            float w1 = __ldg(wp + KTOT);
            float w2 = __ldg(wp + 2*KTOT);
            float px = fmaf(ax0, w0, fmaf(ax1, w1, fmaf(ax2, w2, bx)));
            float py = fmaf(ay0, w0, fmaf(ay1, w1, fmaf(ay2, w2, by)));
            float pz = fmaf(az0, w0, fmaf(az1, w1, fmaf(az2, w2, bz)));
            mnx = fminf(mnx, px); mxx = fmaxf(mxx, px);
            mny = fminf(mny, py); mxy = fmaxf(mxy, py);
            mnz = fminf(mnz, pz); mxz = fmaxf(mxz, pz);
        }
    }
    // warp shuffle reduce (min of negated maxes)
    float r0 = mnx, r1 = -mxx, r2 = mny, r3 = -mxy, r4 = mnz, r5 = -mxz;
    #pragma unroll
    for (int o = 16; o > 0; o >>= 1) {
        r0 = fminf(r0, __shfl_xor_sync(0xffffffffu, r0, o));
        r1 = fminf(r1, __shfl_xor_sync(0xffffffffu, r1, o));
        r2 = fminf(r2, __shfl_xor_sync(0xffffffffu, r2, o));
        r3 = fminf(r3, __shfl_xor_sync(0xffffffffu, r3, o));
        r4 = fminf(r4, __shfl_xor_sync(0xffffffffu, r4, o));
        r5 = fminf(r5, __shfl_xor_sync(0xffffffffu, r5, o));
    }
    if (lane == 0) {
        sRed[0*8+wid] = r0; sRed[1*8+wid] = r1; sRed[2*8+wid] = r2;
        sRed[3*8+wid] = r3; sRed[4*8+wid] = r4; sRed[5*8+wid] = r5;
    }
    __syncthreads();
    if (tid == 0) {
        float m0 = sRed[0], m1 = sRed[8], m2 = sRed[16], m3 = sRed[24], m4 = sRed[32], m5 = sRed[40];
        #pragma unroll
        for (int i = 1; i < 8; i++) {
            m0 = fminf(m0, sRed[0*8+i]); m1 = fminf(m1, sRed[1*8+i]);
            m2 = fminf(m2, sRed[2*8+i]); m3 = fminf(m3, sRed[3*8+i]);
            m4 = fminf(m4, sRed[4*8+i]); m5 = fminf(m5, sRed[5*8+i]);
        }
        float MX = -m1, MY = -m3, MZ = -m5;
        int xlo = max(0, (int)floorf(m0));
        int xhi = min(DIM - 1, (int)floorf(MX) + 1);
        int ylo = max(0, (int)floorf(m2));
        int yhi = min(DIM - 1, (int)floorf(MY) + 1);
        int zlo = max(0, (int)floorf(m4));
        int zhi = min(DIM - 1, (int)floorf(MZ) + 1);
        int nx = xhi - xlo + 1, ny = yhi - ylo + 1, nz = zhi - zlo + 1;
        int mode;
        if (nx <= 0 || ny <= 0 || nz <= 0) mode = 2;                   // fully outside
        else if (nx <= NB && ny <= NB && nz <= NB) mode = 0;           // fixed 8^3 brick
        else mode = 1;                                                 // global fallback
        // anchor clamp: brick [lo, lo+7] always inside volume
        sBox[0] = min(xlo, DIM - NB);
        sBox[1] = min(ylo, DIM - NB);
        sBox[2] = min(zlo, DIM - NB);
        sBox[3] = mode;
    }
    __syncthreads();

    const int xlo = sBox[0], ylo = sBox[1], zlo = sBox[2];
    const int mode = sBox[3];

    const size_t out_base0 = (((size_t)b * C16) * FEATS + f) * KTOT;

    if (mode == 2) {
        #pragma unroll
        for (int it = 0; it < 2; it++) {
            int k = k0 + it*THREADS + tid;
            #pragma unroll
            for (int c = 0; c < C16; c++)
                out[out_base0 + (size_t)c * (FEATS*KTOT) + k] = 0.f;
        }
        return;
    }

    const float* volb = vol + (size_t)b * C16 * DHW;

    // ---------------- Brick load: fixed 8x8x8 x 16ch ----------------
    if (mode == 0) {
        const float* src = volb + (size_t)zlo * HW + ylo * DIM + xlo;
        #pragma unroll
        for (int t = 0; t < BRICK_F / THREADS; t++) {
            int m = t * THREADS + tid;
            int x = m & 7;
            int y = (m >> 3) & 7;
            int z = (m >> 6) & 7;
            int c = m >> 9;
            brick[m] = __ldg(src + (size_t)c * DHW + z * HW + y * DIM + x);
        }
    }
    __syncthreads();

    // ---------------- Main sampling loop ----------------
    if (mode == 0) {
        #pragma unroll
        for (int it = 0; it < 2; it++) {
            int k = k0 + it*THREADS + tid;
            float acc[C16];
            #pragma unroll
            for (int c = 0; c < C16; c++) acc[c] = 0.f;

            #pragma unroll
            for (int s = 0; s < 2; s++) {
                const float* wp = W6 + s*3*KTOT + k;
                float w0 = __ldg(wp);
                float w1 = __ldg(wp + KTOT);
                float w2 = __ldg(wp + 2*KTOT);
                float px = fmaf(ax0, w0, fmaf(ax1, w1, fmaf(ax2, w2, bx)));
                float py = fmaf(ay0, w0, fmaf(ay1, w1, fmaf(ay2, w2, by)));
                float pz = fmaf(az0, w0, fmaf(az1, w1, fmaf(az2, w2, bz)));
                float fx = floorf(px), fy = floorf(py), fz = floorf(pz);
                float tx = px - fx, ty = py - fy, tz = pz - fz;
                int jx0 = (int)fx - xlo, jy0 = (int)fy - ylo, jz0 = (int)fz - zlo;
                int jx1 = jx0 + 1, jy1 = jy0 + 1, jz1 = jz0 + 1;
                float wx0 = 1.f - tx, wx1 = tx;
                float wy0 = 1.f - ty, wy1 = ty;
                float wz0 = 1.f - tz, wz1 = tz;
                // out-of-brick == out-of-volume: zero weight + clamp index
                if ((unsigned)jx0 >= NB) { wx0 = 0.f; jx0 = 0; }
                if ((unsigned)jx1 >= NB) { wx1 = 0.f; jx1 = 0; }
                if ((unsigned)jy0 >= NB) { wy0 = 0.f; jy0 = 0; }
                if ((unsigned)jy1 >= NB) { wy1 = 0.f; jy1 = 0; }
                if ((unsigned)jz0 >= NB) { wz0 = 0.f; jz0 = 0; }
                if ((unsigned)jz1 >= NB) { wz1 = 0.f; jz1 = 0; }
                float sg = s ? -1.f : 1.f;
                float wzy00 = wz0*wy0*sg, wzy01 = wz0*wy1*sg;
                float wzy10 = wz1*wy0*sg, wzy11 = wz1*wy1*sg;
                int r00 = (jz0 << 6) + (jy0 << 3), r01 = (jz0 << 6) + (jy1 << 3);
                int r10 = (jz1 << 6) + (jy0 << 3), r11 = (jz1 << 6) + (jy1 << 3);
                int offs[8] = { r00+jx0, r00+jx1, r01+jx0, r01+jx1,
                                r10+jx0, r10+jx1, r11+jx0, r11+jx1 };
                float wgt[8] = { wzy00*wx0, wzy00*wx1, wzy01*wx0, wzy01*wx1,
                                 wzy10*wx0, wzy10*wx1, wzy11*wx0, wzy11*wx1 };
                #pragma unroll
                for (int j = 0; j < 8; j++) {
                    const float* pj = brick + offs[j];   // one address per corner
                    float w = wgt[j];
                    #pragma unroll
                    for (int c = 0; c < C16; c++)        // LDS with immediate c*PSV*4
                        acc[c] = fmaf(w, pj[c * PSV], acc[c]);
                }
            }
            #pragma unroll
            for (int c = 0; c < C16; c++)
                out[out_base0 + (size_t)c * (FEATS*KTOT) + k] = acc[c];
        }
    } else {
        // mode 1: rare oversized bbox -> direct global gathers
        #pragma unroll
        for (int it = 0; it < 2; it++) {
            int k = k0 + it*THREADS + tid;
            float acc[C16];
            #pragma unroll
            for (int c = 0; c < C16; c++) acc[c] = 0.f;

            #pragma unroll
            for (int s = 0; s < 2; s++) {
                const float* wp = W6 + s*3*KTOT + k;
                float w0 = __ldg(wp);
                float w1 = __ldg(wp + KTOT);
                float w2 = __ldg(wp + 2*KTOT);
                float px = fmaf(ax0, w0, fmaf(ax1, w1, fmaf(ax2, w2, bx)));
                float py = fmaf(ay0, w0, fmaf(ay1, w1, fmaf(ay2, w2, by)));
                float pz = fmaf(az0, w0, fmaf(az1, w1, fmaf(az2, w2, bz)));
                float fx = floorf(px), fy = floorf(py), fz = floorf(pz);
                float tx = px - fx, ty = py - fy, tz = pz - fz;
                int jx0 = (int)fx, jy0 = (int)fy, jz0 = (int)fz;
                int jx1 = jx0 + 1, jy1 = jy0 + 1, jz1 = jz0 + 1;
                float wx0 = 1.f - tx, wx1 = tx;
                float wy0 = 1.f - ty, wy1 = ty;
                float wz0 = 1.f - tz, wz1 = tz;
                if ((unsigned)jx0 >= (unsigned)DIM) { wx0 = 0.f; jx0 = 0; }
                if ((unsigned)jx1 >= (unsigned)DIM) { wx1 = 0.f; jx1 = 0; }
                if ((unsigned)jy0 >= (unsigned)DIM) { wy0 = 0.f; jy0 = 0; }
                if ((unsigned)jy1 >= (unsigned)DIM) { wy1 = 0.f; jy1 = 0; }
                if ((unsigned)jz0 >= (unsigned)DIM) { wz0 = 0.f; jz0 = 0; }
                if ((unsigned)jz1 >= (unsigned)DIM) { wz1 = 0.f; jz1 = 0; }
                float sg = s ? -1.f : 1.f;
                float wzy00 = wz0*wy0*sg, wzy01 = wz0*wy1*sg;
                float wzy10 = wz1*wy0*sg, wzy11 = wz1*wy1*sg;
                int r00 = jz0*HW + jy0*DIM, r01 = jz0*HW + jy1*DIM;
                int r10 = jz1*HW + jy0*DIM, r11 = jz1*HW + jy1*DIM;
                int offs[8] = { r00+jx0, r00+jx1, r01+jx0, r01+jx1,
                                r10+jx0, r10+jx1, r11+jx0, r11+jx1 };
                float wgt[8] = { wzy00*wx0, wzy00*wx1, wzy01*wx0, wzy01*wx1,
                                 wzy10*wx0, wzy10*wx1, wzy11*wx0, wzy11*wx1 };
                #pragma unroll
                for (int j = 0; j < 8; j++) {
                    const float* pj = volb + offs[j];
                    float w = wgt[j];
                    #pragma unroll
                    for (int c = 0; c < C16; c++)
                        acc[c] = fmaf(w, __ldg(pj + (size_t)c * DHW), acc[c]);
                }
            }
            #pragma unroll
            for (int c = 0; c < C16; c++)
                out[out_base0 + (size_t)c * (FEATS*KTOT) + k] = acc[c];
        }
    }
}

extern "C" void kernel_launch(void* const* d_in, const int* in_sizes, int n_in,
                              void* d_out, int out_size)
{
    const float* vol  = (const float*)d_in[0];  // [2,16,96,96,96]
    const float* xyz  = (const float*)d_in[1];  // [2,512,3]
    const float* Amat = (const float*)d_in[2];  // [1024,3,3]
    const float* W6   = (const float*)d_in[3];  // [6,1024]
    float* out = (float*)d_out;                 // [2, 16*512, 1024]

    const int nblocks = 2 * 2 * FEATS;          // 2048
    obelisk_kernel<<<nblocks, THREADS>>>(vol, xyz, Amat, W6, out);
}

// round 4
// speedup vs baseline: 1.2348x; 1.2348x over previous
#include <cuda_runtime.h>

#define THREADS 256
#define C16 16
#define DIM 96
#define HW (DIM*DIM)
#define DHW (DIM*DIM*DIM)
#define FEATS 512
#define KTOT 1024
#define KPB 512            // k per block (KSPLIT=2)
#define NB 8               // fixed brick edge
// padded strides: x=1, y=9, z=72 -> bank = (8*jz + 9*jy + jx) % 32
#define SY 9
#define SZ 72
#define PSV (NB*SZ)        // 576 floats per channel slab
#define BRICK_F (C16*PSV)  // 9216 floats = 36KB

__global__ void __launch_bounds__(THREADS, 5)
obelisk_kernel(const float* __restrict__ vol,
               const float* __restrict__ xyz,
               const float* __restrict__ Amat,
               const float* __restrict__ W6,
               float* __restrict__ out)
{
    __shared__ float brick[BRICK_F];   // 36KB static
    __shared__ float sP[12];
    __shared__ int   sBox[4];          // xlo,ylo,zlo,mode
    __shared__ float sRed[6*8];

    const int tid  = threadIdx.x;
    const int lane = tid & 31;
    const int wid  = tid >> 5;
    const int blk  = blockIdx.x;
    const int pt   = blk >> 1;
    const int kh   = blk & 1;
    const int b    = pt >> 9;
    const int f    = pt & (FEATS - 1);
    const int k0   = kh * KPB;

    if (tid == 0) {
        float x0 = xyz[pt*3+0], x1 = xyz[pt*3+1], x2 = xyz[pt*3+2];
        sP[0] = (x0 + 1.f) * 48.f - 0.5f;
        sP[1] = (x1 + 1.f) * 48.f - 0.5f;
        sP[2] = (x2 + 1.f) * 48.f - 0.5f;
        const float* Ar = Amat + pt * 9;
        sP[3] = 48.f*Ar[6]; sP[4]  = 48.f*Ar[7]; sP[5]  = 48.f*Ar[8];  // x row
        sP[6] = 48.f*Ar[3]; sP[7]  = 48.f*Ar[4]; sP[8]  = 48.f*Ar[5];  // y row
        sP[9] = 48.f*Ar[0]; sP[10] = 48.f*Ar[1]; sP[11] = 48.f*Ar[2];  // z row
    }
    __syncthreads();

    const float bx = sP[0], by = sP[1], bz = sP[2];
    const float ax0 = sP[3], ax1 = sP[4],  ax2 = sP[5];
    const float ay0 = sP[6], ay1 = sP[7],  ay2 = sP[8];
    const float az0 = sP[9], az1 = sP[10], az2 = sP[11];

    // ---------------- Pass 1: bbox of all sample coords (same FP exprs as pass 2)
    float mnx = 1e30f, mxx = -1e30f;
    float mny = 1e30f, mxy = -1e30f;
    float mnz = 1e30f, mxz = -1e30f;
    #pragma unroll
    for (int it = 0; it < 2; it++) {
        int k = k0 + it*THREADS + tid;
        #pragma unroll
        for (int s = 0; s < 2; s++) {
            const float* wp = W6 + s*3*KTOT + k;
            float w0 = __ldg(wp);
            float w1 = __ldg(wp + KTOT);
            float w2 = __ldg(wp + 2*KTOT);
            float px = fmaf(ax0, w0, fmaf(ax1, w1, fmaf(ax2, w2, bx)));
            float py = fmaf(ay0, w0, fmaf(ay1, w1, fmaf(ay2, w2, by)));
            float pz = fmaf(az0, w0, fmaf(az1, w1, fmaf(az2, w2, bz)));
            mnx = fminf(mnx, px); mxx = fmaxf(mxx, px);
            mny = fminf(mny, py); mxy = fmaxf(mxy, py);
            mnz = fminf(mnz, pz); mxz = fmaxf(mxz, pz);
        }
    }
    float r0 = mnx, r1 = -mxx, r2 = mny, r3 = -mxy, r4 = mnz, r5 = -mxz;
    #pragma unroll
    for (int o = 16; o > 0; o >>= 1) {
        r0 = fminf(r0, __shfl_xor_sync(0xffffffffu, r0, o));
        r1 = fminf(r1, __shfl_xor_sync(0xffffffffu, r1, o));
        r2 = fminf(r2, __shfl_xor_sync(0xffffffffu, r2, o));
        r3 = fminf(r3, __shfl_xor_sync(0xffffffffu, r3, o));
        r4 = fminf(r4, __shfl_xor_sync(0xffffffffu, r4, o));
        r5 = fminf(r5, __shfl_xor_sync(0xffffffffu, r5, o));
    }
    if (lane == 0) {
        sRed[0*8+wid] = r0; sRed[1*8+wid] = r1; sRed[2*8+wid] = r2;
        sRed[3*8+wid] = r3; sRed[4*8+wid] = r4; sRed[5*8+wid] = r5;
    }
    __syncthreads();
    if (tid == 0) {
        float m0 = sRed[0], m1 = sRed[8], m2 = sRed[16], m3 = sRed[24], m4 = sRed[32], m5 = sRed[40];
        #pragma unroll
        for (int i = 1; i < 8; i++) {
            m0 = fminf(m0, sRed[0*8+i]); m1 = fminf(m1, sRed[1*8+i]);
            m2 = fminf(m2, sRed[2*8+i]); m3 = fminf(m3, sRed[3*8+i]);
            m4 = fminf(m4, sRed[4*8+i]); m5 = fminf(m5, sRed[5*8+i]);
        }
        float MX = -m1, MY = -m3, MZ = -m5;
        int xlo = max(0, (int)floorf(m0));
        int xhi = min(DIM - 1, (int)floorf(MX) + 1);
        int ylo = max(0, (int)floorf(m2));
        int yhi = min(DIM - 1, (int)floorf(MY) + 1);
        int zlo = max(0, (int)floorf(m4));
        int zhi = min(DIM - 1, (int)floorf(MZ) + 1);
        int nx = xhi - xlo + 1, ny = yhi - ylo + 1, nz = zhi - zlo + 1;
        int mode;
        if (nx <= 0 || ny <= 0 || nz <= 0) mode = 2;                   // fully outside
        else if (nx <= NB && ny <= NB && nz <= NB) mode = 0;           // fixed 8^3 brick
        else mode = 1;                                                 // global fallback
        // anchor clamp: brick [lo, lo+7] always inside volume
        sBox[0] = min(xlo, DIM - NB);
        sBox[1] = min(ylo, DIM - NB);
        sBox[2] = min(zlo, DIM - NB);
        sBox[3] = mode;
    }
    __syncthreads();

    const int xlo = sBox[0], ylo = sBox[1], zlo = sBox[2];
    const int mode = sBox[3];

    const size_t out_base0 = (((size_t)b * C16) * FEATS + f) * KTOT;

    if (mode == 2) {
        #pragma unroll
        for (int it = 0; it < 2; it++) {
            int k = k0 + it*THREADS + tid;
            #pragma unroll
            for (int c = 0; c < C16; c++)
                out[out_base0 + (size_t)c * (FEATS*KTOT) + k] = 0.f;
        }
        return;
    }

    const float* volb = vol + (size_t)b * C16 * DHW;

    // ---------------- Brick load: fixed 8x8x8 x 16ch, padded layout ----------------
    if (mode == 0) {
        const float* src = volb + (size_t)zlo * HW + ylo * DIM + xlo;
        #pragma unroll
        for (int t = 0; t < (C16*NB*NB*NB) / THREADS; t++) {
            int m = t * THREADS + tid;
            int x = m & 7;
            int y = (m >> 3) & 7;
            int z = (m >> 6) & 7;
            int c = m >> 9;
            brick[c * PSV + z * SZ + y * SY + x] =
                __ldg(src + (size_t)c * DHW + z * HW + y * DIM + x);
        }
    }
    __syncthreads();

    // ---------------- Main sampling loop ----------------
    if (mode == 0) {
        #pragma unroll
        for (int it = 0; it < 2; it++) {
            int k = k0 + it*THREADS + tid;
            float acc[C16];
            #pragma unroll
            for (int c = 0; c < C16; c++) acc[c] = 0.f;

            #pragma unroll
            for (int s = 0; s < 2; s++) {
                const float* wp = W6 + s*3*KTOT + k;
                float w0 = __ldg(wp);
                float w1 = __ldg(wp + KTOT);
                float w2 = __ldg(wp + 2*KTOT);
                float px = fmaf(ax0, w0, fmaf(ax1, w1, fmaf(ax2, w2, bx)));
                float py = fmaf(ay0, w0, fmaf(ay1, w1, fmaf(ay2, w2, by)));
                float pz = fmaf(az0, w0, fmaf(az1, w1, fmaf(az2, w2, bz)));
                float fx = floorf(px), fy = floorf(py), fz = floorf(pz);
                float tx = px - fx, ty = py - fy, tz = pz - fz;
                int jx0 = (int)fx - xlo, jy0 = (int)fy - ylo, jz0 = (int)fz - zlo;
                int jx1 = jx0 + 1, jy1 = jy0 + 1, jz1 = jz0 + 1;
                float wx0 = 1.f - tx, wx1 = tx;
                float wy0 = 1.f - ty, wy1 = ty;
                float wz0 = 1.f - tz, wz1 = tz;
                // out-of-brick == out-of-volume: zero weight + clamp index
                if ((unsigned)jx0 >= NB) { wx0 = 0.f; jx0 = 0; }
                if ((unsigned)jx1 >= NB) { wx1 = 0.f; jx1 = 0; }
                if ((unsigned)jy0 >= NB) { wy0 = 0.f; jy0 = 0; }
                if ((unsigned)jy1 >= NB) { wy1 = 0.f; jy1 = 0; }
                if ((unsigned)jz0 >= NB) { wz0 = 0.f; jz0 = 0; }
                if ((unsigned)jz1 >= NB) { wz1 = 0.f; jz1 = 0; }
                float sg = s ? -1.f : 1.f;
                float wzy00 = wz0*wy0*sg, wzy01 = wz0*wy1*sg;
                float wzy10 = wz1*wy0*sg, wzy11 = wz1*wy1*sg;
                int r00 = jz0*SZ + jy0*SY, r01 = jz0*SZ + jy1*SY;
                int r10 = jz1*SZ + jy0*SY, r11 = jz1*SZ + jy1*SY;
                int offs[8] = { r00+jx0, r00+jx1, r01+jx0, r01+jx1,
                                r10+jx0, r10+jx1, r11+jx0, r11+jx1 };
                float wgt[8] = { wzy00*wx0, wzy00*wx1, wzy01*wx0, wzy01*wx1,
                                 wzy10*wx0, wzy10*wx1, wzy11*wx0, wzy11*wx1 };
                #pragma unroll
                for (int j = 0; j < 8; j++) {
                    const float* pj = brick + offs[j];   // one address per corner
                    float w = wgt[j];
                    #pragma unroll
                    for (int c = 0; c < C16; c++)        // LDS with immediate c*PSV*4
                        acc[c] = fmaf(w, pj[c * PSV], acc[c]);
                }
            }
            #pragma unroll
            for (int c = 0; c < C16; c++)
                out[out_base0 + (size_t)c * (FEATS*KTOT) + k] = acc[c];
        }
    } else {
        // mode 1: rare oversized bbox -> direct global gathers
        #pragma unroll
        for (int it = 0; it < 2; it++) {
            int k = k0 + it*THREADS + tid;
            float acc[C16];
            #pragma unroll
            for (int c = 0; c < C16; c++) acc[c] = 0.f;

            #pragma unroll
            for (int s = 0; s < 2; s++) {
                const float* wp = W6 + s*3*KTOT + k;
                float w0 = __ldg(wp);
                float w1 = __ldg(wp + KTOT);
                float w2 = __ldg(wp + 2*KTOT);
                float px = fmaf(ax0, w0, fmaf(ax1, w1, fmaf(ax2, w2, bx)));
                float py = fmaf(ay0, w0, fmaf(ay1, w1, fmaf(ay2, w2, by)));
                float pz = fmaf(az0, w0, fmaf(az1, w1, fmaf(az2, w2, bz)));
                float fx = floorf(px), fy = floorf(py), fz = floorf(pz);
                float tx = px - fx, ty = py - fy, tz = pz - fz;
                int jx0 = (int)fx, jy0 = (int)fy, jz0 = (int)fz;
                int jx1 = jx0 + 1, jy1 = jy0 + 1, jz1 = jz0 + 1;
                float wx0 = 1.f - tx, wx1 = tx;
                float wy0 = 1.f - ty, wy1 = ty;
                float wz0 = 1.f - tz, wz1 = tz;
                if ((unsigned)jx0 >= (unsigned)DIM) { wx0 = 0.f; jx0 = 0; }
                if ((unsigned)jx1 >= (unsigned)DIM) { wx1 = 0.f; jx1 = 0; }
                if ((unsigned)jy0 >= (unsigned)DIM) { wy0 = 0.f; jy0 = 0; }
                if ((unsigned)jy1 >= (unsigned)DIM) { wy1 = 0.f; jy1 = 0; }
                if ((unsigned)jz0 >= (unsigned)DIM) { wz0 = 0.f; jz0 = 0; }
                if ((unsigned)jz1 >= (unsigned)DIM) { wz1 = 0.f; jz1 = 0; }
                float sg = s ? -1.f : 1.f;
                float wzy00 = wz0*wy0*sg, wzy01 = wz0*wy1*sg;
                float wzy10 = wz1*wy0*sg, wzy11 = wz1*wy1*sg;
                int r00 = jz0*HW + jy0*DIM, r01 = jz0*HW + jy1*DIM;
                int r10 = jz1*HW + jy0*DIM, r11 = jz1*HW + jy1*DIM;
                int offs[8] = { r00+jx0, r00+jx1, r01+jx0, r01+jx1,
                                r10+jx0, r10+jx1, r11+jx0, r11+jx1 };
                float wgt[8] = { wzy00*wx0, wzy00*wx1, wzy01*wx0, wzy01*wx1,
                                 wzy10*wx0, wzy10*wx1, wzy11*wx0, wzy11*wx1 };
                #pragma unroll
                for (int j = 0; j < 8; j++) {
                    const float* pj = volb + offs[j];
                    float w = wgt[j];
                    #pragma unroll
                    for (int c = 0; c < C16; c++)
                        acc[c] = fmaf(w, __ldg(pj + (size_t)c * DHW), acc[c]);
                }
            }
            #pragma unroll
            for (int c = 0; c < C16; c++)
                out[out_base0 + (size_t)c * (FEATS*KTOT) + k] = acc[c];
        }
    }
}

extern "C" void kernel_launch(void* const* d_in, const int* in_sizes, int n_in,
                              void* d_out, int out_size)
{
    const float* vol  = (const float*)d_in[0];  // [2,16,96,96,96]
    const float* xyz  = (const float*)d_in[1];  // [2,512,3]
    const float* Amat = (const float*)d_in[2];  // [1024,3,3]
    const float* W6   = (const float*)d_in[3];  // [6,1024]
    float* out = (float*)d_out;                 // [2, 16*512, 1024]

    const int nblocks = 2 * 2 * FEATS;          // 2048
    obelisk_kernel<<<nblocks, THREADS>>>(vol, xyz, Amat, W6, out);
}